// round 6
// baseline (speedup 1.0000x reference)
#include <cuda_runtime.h>
#include <cuda_bf16.h>

// GINConv forward: out = segment_sum(X[ci]) @ W  ==  segment_sum((X@W)[ci])
// Kernel 1: Y = X @ W   (tiled 64x64, f32x2 packed FMA)  [proven R3/R5 version]
// Kernel 2: out = segment_sum(Y[ci])  (half-warp per node, 8-deep gather
//           pipeline + int4 index loads for MLP against L2 latency)

#define D_FEAT 64
#define N_NODES_MAX 100000

// Scratch for Y (25.6 MB). __device__ global: allowed (no dynamic alloc).
__device__ __align__(16) float g_Y[(size_t)N_NODES_MAX * D_FEAT];

// ---- packed f32x2 helpers (sm_103a) ----
__device__ __forceinline__ unsigned long long pk2(float lo, float hi) {
    unsigned long long r;
    asm("mov.b64 %0, {%1, %2};" : "=l"(r) : "f"(lo), "f"(hi));
    return r;
}
__device__ __forceinline__ void unpk2(unsigned long long v, float& lo, float& hi) {
    asm("mov.b64 {%0, %1}, %2;" : "=f"(lo), "=f"(hi) : "l"(v));
}
__device__ __forceinline__ void fma2(unsigned long long& d,
                                     unsigned long long a,
                                     unsigned long long b) {
    asm("fma.rn.f32x2 %0, %1, %2, %0;" : "+l"(d) : "l"(a), "l"(b));
}

__device__ __forceinline__ void acc4(float4& a, const float4 v) {
    a.x += v.x; a.y += v.y; a.z += v.z; a.w += v.w;
}

// ================= Kernel 1: Y = X @ W =================
__global__ __launch_bounds__(256) void gemm_xw_kernel(
    const float* __restrict__ X,
    const float* __restrict__ W,
    float* __restrict__ Y,
    int n_rows)
{
    __shared__ __align__(16) float Xs[D_FEAT][68];               // 17.4 KB
    __shared__ __align__(16) unsigned long long Wp[D_FEAT * 32]; // 16 KB

    const int tid = threadIdx.x;
    const int ty = tid >> 4;
    const int tx = tid & 15;
    const int base = blockIdx.x * 64;

    #pragma unroll
    for (int i = tid; i < 1024; i += 256) {
        const float4 w4 = reinterpret_cast<const float4*>(W)[i];
        const int k = i >> 4, p = i & 15;
        Wp[k * 32 + 2 * p + 0] = pk2(w4.x, w4.y);
        Wp[k * 32 + 2 * p + 1] = pk2(w4.z, w4.w);
    }
    #pragma unroll
    for (int i = tid; i < 1024; i += 256) {
        const int r = i >> 4, q = i & 15;
        float4 v = make_float4(0.f, 0.f, 0.f, 0.f);
        if (base + r < n_rows)
            v = reinterpret_cast<const float4*>(X)[(size_t)(base + r) * 16 + q];
        *reinterpret_cast<float4*>(&Xs[r][q * 4]) = v;
    }
    __syncthreads();

    unsigned long long acc[4][2] = {};

    #pragma unroll 4
    for (int k = 0; k < D_FEAT; ++k) {
        const longlong2 w2 =
            reinterpret_cast<const longlong2*>(Wp + k * 32)[tx];
        #pragma unroll
        for (int j = 0; j < 4; ++j) {
            const float x = Xs[ty * 4 + j][k];
            const unsigned long long xx = pk2(x, x);
            fma2(acc[j][0], xx, (unsigned long long)w2.x);
            fma2(acc[j][1], xx, (unsigned long long)w2.y);
        }
    }

    #pragma unroll
    for (int j = 0; j < 4; ++j) {
        const int row = base + ty * 4 + j;
        if (row < n_rows) {
            float a, b, c, d;
            unpk2(acc[j][0], a, b);
            unpk2(acc[j][1], c, d);
            reinterpret_cast<float4*>(Y)[(size_t)row * 16 + tx] =
                make_float4(a, b, c, d);
        }
    }
}

// ============ Kernel 2: out = segment_sum(Y[ci]) ============
// Half-warp (16 lanes) per node; lane fl owns float4 chunk fl of the row.
// 8-deep load pipeline (16 outstanding LDG.128/warp) + int4 index loads.
__global__ __launch_bounds__(128, 8) void gather_sum_kernel(
    const float4* __restrict__ Y4,
    const int* __restrict__ rp,
    const int* __restrict__ ci,
    float4* __restrict__ out4,
    int n_nodes)
{
    const int tid  = threadIdx.x;
    const int half = tid >> 4;
    const int fl   = tid & 15;
    const int node = blockIdx.x * 8 + half;
    if (node >= n_nodes) return;

    const int start = __ldg(&rp[node]);
    const int end   = __ldg(&rp[node + 1]);

    const int4* __restrict__ ci4 = reinterpret_cast<const int4*>(ci);

    float4 a0 = make_float4(0.f, 0.f, 0.f, 0.f);
    float4 a1 = a0, a2 = a0, a3 = a0;

    int e = start;

    // Peel to 4-alignment for int4 index loads
    int pre = (4 - (e & 3)) & 3;
    if (pre > end - e) pre = end - e;
    for (int i = 0; i < pre; ++i, ++e) {
        const int c = __ldg(&ci[e]);
        acc4(a0, __ldg(&Y4[(size_t)c * 16 + fl]));
    }

    // Main: 8 edges per iteration, 8 independent gathers in flight
    for (; e + 8 <= end; e += 8) {
        const int4 ca = __ldg(&ci4[e >> 2]);
        const int4 cb = __ldg(&ci4[(e >> 2) + 1]);
        const float4 v0 = __ldg(&Y4[(size_t)ca.x * 16 + fl]);
        const float4 v1 = __ldg(&Y4[(size_t)ca.y * 16 + fl]);
        const float4 v2 = __ldg(&Y4[(size_t)ca.z * 16 + fl]);
        const float4 v3 = __ldg(&Y4[(size_t)ca.w * 16 + fl]);
        const float4 v4 = __ldg(&Y4[(size_t)cb.x * 16 + fl]);
        const float4 v5 = __ldg(&Y4[(size_t)cb.y * 16 + fl]);
        const float4 v6 = __ldg(&Y4[(size_t)cb.z * 16 + fl]);
        const float4 v7 = __ldg(&Y4[(size_t)cb.w * 16 + fl]);
        acc4(a0, v0); acc4(a1, v1); acc4(a2, v2); acc4(a3, v3);
        acc4(a0, v4); acc4(a1, v5); acc4(a2, v6); acc4(a3, v7);
    }

    // 4-edge chunk
    if (e + 4 <= end) {
        const int4 ca = __ldg(&ci4[e >> 2]);
        const float4 v0 = __ldg(&Y4[(size_t)ca.x * 16 + fl]);
        const float4 v1 = __ldg(&Y4[(size_t)ca.y * 16 + fl]);
        const float4 v2 = __ldg(&Y4[(size_t)ca.z * 16 + fl]);
        const float4 v3 = __ldg(&Y4[(size_t)ca.w * 16 + fl]);
        acc4(a0, v0); acc4(a1, v1); acc4(a2, v2); acc4(a3, v3);
        e += 4;
    }

    // Scalar tail
    for (; e < end; ++e) {
        const int c = __ldg(&ci[e]);
        acc4(a0, __ldg(&Y4[(size_t)c * 16 + fl]));
    }

    float4 r;
    r.x = (a0.x + a1.x) + (a2.x + a3.x);
    r.y = (a0.y + a1.y) + (a2.y + a3.y);
    r.z = (a0.z + a1.z) + (a2.z + a3.z);
    r.w = (a0.w + a1.w) + (a2.w + a3.w);

    out4[(size_t)node * 16 + fl] = r;
}

extern "C" void kernel_launch(void* const* d_in, const int* in_sizes, int n_in,
                              void* d_out, int out_size) {
    const float* X  = (const float*)d_in[0];   // [100000, 64]
    const float* W  = (const float*)d_in[1];   // [64, 64]
    const int*   rp = (const int*)d_in[2];     // [100001]
    const int*   ci = (const int*)d_in[3];     // [1600000]
    float* out = (float*)d_out;                // [100000, 64]

    const int n_nodes = in_sizes[2] - 1;       // 100000

    float* Yptr = nullptr;
    cudaGetSymbolAddress((void**)&Yptr, g_Y);

    const int blocks1 = (n_nodes + 63) / 64;
    gemm_xw_kernel<<<blocks1, 256>>>(X, W, Yptr, n_nodes);

    const int blocks2 = (n_nodes + 7) / 8;
    gather_sum_kernel<<<blocks2, 128>>>(
        reinterpret_cast<const float4*>(Yptr), rp, ci,
        reinterpret_cast<float4*>(out), n_nodes);
}

// round 7
// speedup vs baseline: 1.0144x; 1.0144x over previous
#include <cuda_runtime.h>
#include <cuda_bf16.h>

// GINConv forward: out = segment_sum(X[ci]) @ W  ==  segment_sum((X@W)[ci])
// Kernel 1: Y = X @ W   (tiled 64x64, f32x2 packed FMA)  [proven]
// Kernel 2: out = segment_sum(Y[ci])  (half-warp per node, 4 float4 gathers
//           per iter, int4 index prefetch pipelined one iteration ahead)

#define D_FEAT 64
#define N_NODES_MAX 100000

// Scratch for Y (25.6 MB). __device__ global: allowed (no dynamic alloc).
__device__ __align__(16) float g_Y[(size_t)N_NODES_MAX * D_FEAT];

// ---- packed f32x2 helpers (sm_103a) ----
__device__ __forceinline__ unsigned long long pk2(float lo, float hi) {
    unsigned long long r;
    asm("mov.b64 %0, {%1, %2};" : "=l"(r) : "f"(lo), "f"(hi));
    return r;
}
__device__ __forceinline__ void unpk2(unsigned long long v, float& lo, float& hi) {
    asm("mov.b64 {%0, %1}, %2;" : "=f"(lo), "=f"(hi) : "l"(v));
}
__device__ __forceinline__ void fma2(unsigned long long& d,
                                     unsigned long long a,
                                     unsigned long long b) {
    asm("fma.rn.f32x2 %0, %1, %2, %0;" : "+l"(d) : "l"(a), "l"(b));
}
__device__ __forceinline__ void acc4(float4& a, const float4 v) {
    a.x += v.x; a.y += v.y; a.z += v.z; a.w += v.w;
}

// ================= Kernel 1: Y = X @ W =================
__global__ __launch_bounds__(256) void gemm_xw_kernel(
    const float* __restrict__ X,
    const float* __restrict__ W,
    float* __restrict__ Y,
    int n_rows)
{
    __shared__ __align__(16) float Xs[D_FEAT][68];               // 17.4 KB
    __shared__ __align__(16) unsigned long long Wp[D_FEAT * 32]; // 16 KB

    const int tid = threadIdx.x;
    const int ty = tid >> 4;
    const int tx = tid & 15;
    const int base = blockIdx.x * 64;

    #pragma unroll
    for (int i = tid; i < 1024; i += 256) {
        const float4 w4 = reinterpret_cast<const float4*>(W)[i];
        const int k = i >> 4, p = i & 15;
        Wp[k * 32 + 2 * p + 0] = pk2(w4.x, w4.y);
        Wp[k * 32 + 2 * p + 1] = pk2(w4.z, w4.w);
    }
    #pragma unroll
    for (int i = tid; i < 1024; i += 256) {
        const int r = i >> 4, q = i & 15;
        float4 v = make_float4(0.f, 0.f, 0.f, 0.f);
        if (base + r < n_rows)
            v = reinterpret_cast<const float4*>(X)[(size_t)(base + r) * 16 + q];
        *reinterpret_cast<float4*>(&Xs[r][q * 4]) = v;
    }
    __syncthreads();

    unsigned long long acc[4][2] = {};

    #pragma unroll 4
    for (int k = 0; k < D_FEAT; ++k) {
        const longlong2 w2 =
            reinterpret_cast<const longlong2*>(Wp + k * 32)[tx];
        #pragma unroll
        for (int j = 0; j < 4; ++j) {
            const float x = Xs[ty * 4 + j][k];
            const unsigned long long xx = pk2(x, x);
            fma2(acc[j][0], xx, (unsigned long long)w2.x);
            fma2(acc[j][1], xx, (unsigned long long)w2.y);
        }
    }

    #pragma unroll
    for (int j = 0; j < 4; ++j) {
        const int row = base + ty * 4 + j;
        if (row < n_rows) {
            float a, b, c, d;
            unpk2(acc[j][0], a, b);
            unpk2(acc[j][1], c, d);
            reinterpret_cast<float4*>(Y)[(size_t)row * 16 + tx] =
                make_float4(a, b, c, d);
        }
    }
}

// ============ Kernel 2: out = segment_sum(Y[ci]) ============
// Half-warp (16 lanes) per node; lane fl owns float4 chunk fl of the row.
// Indices prefetched one iteration ahead (int4) so the ci->gather chain is
// off the critical path; 4 independent gathers in flight per half-warp.
__global__ __launch_bounds__(128, 12) void gather_sum_kernel(
    const float4* __restrict__ Y4,
    const int* __restrict__ rp,
    const int* __restrict__ ci,
    float4* __restrict__ out4,
    int n_nodes)
{
    const int tid  = threadIdx.x;
    const int half = tid >> 4;
    const int fl   = tid & 15;
    const int node = blockIdx.x * 8 + half;
    if (node >= n_nodes) return;

    const int start = __ldg(&rp[node]);
    const int end   = __ldg(&rp[node + 1]);

    const int4* __restrict__ ci4 = reinterpret_cast<const int4*>(ci);

    float4 a0 = make_float4(0.f, 0.f, 0.f, 0.f);
    float4 a1 = a0;

    int e = start;

    // Peel to 16B alignment for int4 index loads
    int pre = (4 - (e & 3)) & 3;
    if (pre > end - e) pre = end - e;
    for (int i = 0; i < pre; ++i, ++e) {
        const int c = __ldg(&ci[e]);
        acc4(a0, __ldg(&Y4[(size_t)c * 16 + fl]));
    }

    const int nq = (end - e) >> 2;   // full quads
    if (nq > 0) {
        const int qbase = e >> 2;
        int4 nxt = __ldg(&ci4[qbase]);
        for (int q = 0; q < nq; ++q) {
            const int4 cur = nxt;
            if (q + 1 < nq) nxt = __ldg(&ci4[qbase + q + 1]);  // prefetch
            const float4 v0 = __ldg(&Y4[(size_t)cur.x * 16 + fl]);
            const float4 v1 = __ldg(&Y4[(size_t)cur.y * 16 + fl]);
            const float4 v2 = __ldg(&Y4[(size_t)cur.z * 16 + fl]);
            const float4 v3 = __ldg(&Y4[(size_t)cur.w * 16 + fl]);
            acc4(a0, v0); acc4(a1, v1);
            acc4(a0, v2); acc4(a1, v3);
        }
        e += nq * 4;
    }

    // Scalar tail (<4 edges)
    for (; e < end; ++e) {
        const int c = __ldg(&ci[e]);
        acc4(a0, __ldg(&Y4[(size_t)c * 16 + fl]));
    }

    float4 r;
    r.x = a0.x + a1.x;
    r.y = a0.y + a1.y;
    r.z = a0.z + a1.z;
    r.w = a0.w + a1.w;

    out4[(size_t)node * 16 + fl] = r;   // warp = 2 consecutive rows: coalesced
}

extern "C" void kernel_launch(void* const* d_in, const int* in_sizes, int n_in,
                              void* d_out, int out_size) {
    const float* X  = (const float*)d_in[0];   // [100000, 64]
    const float* W  = (const float*)d_in[1];   // [64, 64]
    const int*   rp = (const int*)d_in[2];     // [100001]
    const int*   ci = (const int*)d_in[3];     // [1600000]
    float* out = (float*)d_out;                // [100000, 64]

    const int n_nodes = in_sizes[2] - 1;       // 100000

    float* Yptr = nullptr;
    cudaGetSymbolAddress((void**)&Yptr, g_Y);

    const int blocks1 = (n_nodes + 63) / 64;
    gemm_xw_kernel<<<blocks1, 256>>>(X, W, Yptr, n_nodes);

    const int blocks2 = (n_nodes + 7) / 8;
    gather_sum_kernel<<<blocks2, 128>>>(
        reinterpret_cast<const float4*>(Yptr), rp, ci,
        reinterpret_cast<float4*>(out), n_nodes);
}

// round 8
// speedup vs baseline: 1.1181x; 1.1022x over previous
#include <cuda_runtime.h>
#include <cuda_bf16.h>
#include <cuda_fp16.h>

// GINConv forward: out = segment_sum(X[ci]) @ W  ==  segment_sum((X@W)[ci])
// Kernel 1: Y = X @ W, stored as fp16 (halves gather traffic; fp32 accum math)
// Kernel 2: out = segment_sum(Y[ci])  — exact R5 schedule (proven 46us in
//           fp32), now one 128B line per edge instead of two.

#define D_FEAT 64
#define N_NODES_MAX 100000

// Scratch for Y in fp16 (12.8 MB). __device__ global: allowed (no alloc).
__device__ __align__(16) __half g_Yh[(size_t)N_NODES_MAX * D_FEAT];

// ---- packed f32x2 helpers (sm_103a) ----
__device__ __forceinline__ unsigned long long pk2(float lo, float hi) {
    unsigned long long r;
    asm("mov.b64 %0, {%1, %2};" : "=l"(r) : "f"(lo), "f"(hi));
    return r;
}
__device__ __forceinline__ void unpk2(unsigned long long v, float& lo, float& hi) {
    asm("mov.b64 {%0, %1}, %2;" : "=f"(lo), "=f"(hi) : "l"(v));
}
__device__ __forceinline__ void fma2(unsigned long long& d,
                                     unsigned long long a,
                                     unsigned long long b) {
    asm("fma.rn.f32x2 %0, %1, %2, %0;" : "+l"(d) : "l"(a), "l"(b));
}

// Accumulate 4 fp16 values (one uint2) into a float4 accumulator.
__device__ __forceinline__ void acch(float4& a, const uint2 u) {
    const __half2 h0 = *reinterpret_cast<const __half2*>(&u.x);
    const __half2 h1 = *reinterpret_cast<const __half2*>(&u.y);
    const float2 f0 = __half22float2(h0);
    const float2 f1 = __half22float2(h1);
    a.x += f0.x; a.y += f0.y; a.z += f1.x; a.w += f1.y;
}

// ================= Kernel 1: Y = X @ W (fp16 out) =================
// 64-row tile per block, 256 threads as 16x16, each thread a 4x4 micro-tile.
__global__ __launch_bounds__(256) void gemm_xw_kernel(
    const float* __restrict__ X,
    const float* __restrict__ W,
    uint2* __restrict__ Yh2,      // [n_rows * 16] uint2 (4 halves each)
    int n_rows)
{
    __shared__ __align__(16) float Xs[D_FEAT][68];               // 17.4 KB
    __shared__ __align__(16) unsigned long long Wp[D_FEAT * 32]; // 16 KB

    const int tid = threadIdx.x;
    const int ty = tid >> 4;       // row group
    const int tx = tid & 15;       // col group
    const int base = blockIdx.x * 64;

    #pragma unroll
    for (int i = tid; i < 1024; i += 256) {
        const float4 w4 = reinterpret_cast<const float4*>(W)[i];
        const int k = i >> 4, p = i & 15;
        Wp[k * 32 + 2 * p + 0] = pk2(w4.x, w4.y);
        Wp[k * 32 + 2 * p + 1] = pk2(w4.z, w4.w);
    }
    #pragma unroll
    for (int i = tid; i < 1024; i += 256) {
        const int r = i >> 4, q = i & 15;
        float4 v = make_float4(0.f, 0.f, 0.f, 0.f);
        if (base + r < n_rows)
            v = reinterpret_cast<const float4*>(X)[(size_t)(base + r) * 16 + q];
        *reinterpret_cast<float4*>(&Xs[r][q * 4]) = v;
    }
    __syncthreads();

    unsigned long long acc[4][2] = {};

    #pragma unroll 4
    for (int k = 0; k < D_FEAT; ++k) {
        const longlong2 w2 =
            reinterpret_cast<const longlong2*>(Wp + k * 32)[tx];
        #pragma unroll
        for (int j = 0; j < 4; ++j) {
            const float x = Xs[ty * 4 + j][k];
            const unsigned long long xx = pk2(x, x);
            fma2(acc[j][0], xx, (unsigned long long)w2.x);
            fma2(acc[j][1], xx, (unsigned long long)w2.y);
        }
    }

    #pragma unroll
    for (int j = 0; j < 4; ++j) {
        const int row = base + ty * 4 + j;
        if (row < n_rows) {
            float a, b, c, d;
            unpk2(acc[j][0], a, b);
            unpk2(acc[j][1], c, d);
            const __half2 h0 = __float22half2_rn(make_float2(a, b));
            const __half2 h1 = __float22half2_rn(make_float2(c, d));
            uint2 u;
            u.x = *reinterpret_cast<const unsigned*>(&h0);
            u.y = *reinterpret_cast<const unsigned*>(&h1);
            Yh2[(size_t)row * 16 + tx] = u;
        }
    }
}

// ============ Kernel 2: out = segment_sum(Y[ci]) ============
// Half-warp (16 lanes) per node; lane fl owns 4 halves (uint2) of the row.
// One 128B line per edge per half-warp. 4-way unrolled independent gathers.
__global__ __launch_bounds__(128, 12) void gather_sum_kernel(
    const uint2* __restrict__ Yh2,
    const int* __restrict__ rp,
    const int* __restrict__ ci,
    float4* __restrict__ out4,
    int n_nodes)
{
    const int tid  = threadIdx.x;
    const int half = tid >> 4;     // half-warp id within block: 0..7
    const int fl   = tid & 15;     // uint2 index within the 128B row
    const int node = blockIdx.x * 8 + half;
    if (node >= n_nodes) return;

    const int start = __ldg(&rp[node]);
    const int end   = __ldg(&rp[node + 1]);

    float4 a0 = make_float4(0.f, 0.f, 0.f, 0.f);
    float4 a1 = a0, a2 = a0, a3 = a0;

    int e = start;
    for (; e + 4 <= end; e += 4) {
        const int c0 = __ldg(&ci[e + 0]);
        const int c1 = __ldg(&ci[e + 1]);
        const int c2 = __ldg(&ci[e + 2]);
        const int c3 = __ldg(&ci[e + 3]);
        const uint2 v0 = __ldg(&Yh2[(size_t)c0 * 16 + fl]);
        const uint2 v1 = __ldg(&Yh2[(size_t)c1 * 16 + fl]);
        const uint2 v2 = __ldg(&Yh2[(size_t)c2 * 16 + fl]);
        const uint2 v3 = __ldg(&Yh2[(size_t)c3 * 16 + fl]);
        acch(a0, v0);
        acch(a1, v1);
        acch(a2, v2);
        acch(a3, v3);
    }
    for (; e < end; ++e) {
        const int c = __ldg(&ci[e]);
        const uint2 v = __ldg(&Yh2[(size_t)c * 16 + fl]);
        acch(a0, v);
    }

    float4 r;
    r.x = (a0.x + a1.x) + (a2.x + a3.x);
    r.y = (a0.y + a1.y) + (a2.y + a3.y);
    r.z = (a0.z + a1.z) + (a2.z + a3.z);
    r.w = (a0.w + a1.w) + (a2.w + a3.w);

    out4[(size_t)node * 16 + fl] = r;   // warp = 2 consecutive rows: coalesced
}

extern "C" void kernel_launch(void* const* d_in, const int* in_sizes, int n_in,
                              void* d_out, int out_size) {
    const float* X  = (const float*)d_in[0];   // [100000, 64]
    const float* W  = (const float*)d_in[1];   // [64, 64]
    const int*   rp = (const int*)d_in[2];     // [100001]
    const int*   ci = (const int*)d_in[3];     // [1600000]
    float* out = (float*)d_out;                // [100000, 64]

    const int n_nodes = in_sizes[2] - 1;       // 100000

    __half* Yptr = nullptr;
    cudaGetSymbolAddress((void**)&Yptr, g_Yh);
    uint2* Yh2 = reinterpret_cast<uint2*>(Yptr);

    const int blocks1 = (n_nodes + 63) / 64;
    gemm_xw_kernel<<<blocks1, 256>>>(X, W, Yh2, n_nodes);

    const int blocks2 = (n_nodes + 7) / 8;
    gather_sum_kernel<<<blocks2, 128>>>(
        Yh2, rp, ci, reinterpret_cast<float4*>(out), n_nodes);
}